// round 2
// baseline (speedup 1.0000x reference)
#include <cuda_runtime.h>

#define N_K_STEPS 512
#define N_STATE   128
#define N_INPUT   32
#define HIDDEN    256
#define FAN_IN    161   /* 1 + 128 + 32 */

// Tsit5 tableau
__constant__ float c_C[6] = {0.0f, 0.161f, 0.327f, 0.9f, 0.9800255409045097f, 1.0f};
__constant__ float c_A[5][5] = {
  {0.161f, 0.f, 0.f, 0.f, 0.f},
  {-0.008480655492356989f, 0.335480655492357f, 0.f, 0.f, 0.f},
  {2.8971530571054935f, -6.359448489975075f, 4.3622954328695815f, 0.f, 0.f},
  {5.325864828439257f, -11.748883564062828f, 7.4955393428898365f, -0.09249506636175525f, 0.f},
  {5.86145544294642f, -12.92096931784711f, 8.159367898576159f, -0.071584973281401f, -0.028269050394068383f}
};
__constant__ float c_B[6] = {0.09646076681806523f, 0.01f, 0.4798896504144996f,
                             1.379008574103742f, -3.290069515436081f, 2.324710524099774f};

struct SmemLayout {
  float2 w2[128 * 128];   // W2 packed pairs: [k2][o] ; k2 = k/2, o = output idx
  float2 zs2[82];         // z vector as 82 pairs (164 floats, [161..163] zero pad)
  float  hs[256];         // hidden activations
  float  partial[256];    // stage-2 partial sums
  float  ksh[5][128];     // k1..k5
  float  ustg[6][32];     // interpolated u for stages 1..5 ([0] unused)
};

__device__ __forceinline__ float2 ffma2f(float2 a, float2 b, float2 c) {
  union { float2 f; unsigned long long u; } ua, ub, uc;
  ua.f = a; ub.f = b; uc.f = c;
  asm("fma.rn.f32x2 %0, %1, %2, %0;" : "+l"(uc.u) : "l"(ua.u), "l"(ub.u));
  return uc.f;
}

__global__ __launch_bounds__(256, 1)
void ode_tsit5_kernel(const float* __restrict__ ts, const float* __restrict__ y0,
                      const float* __restrict__ us, const float* __restrict__ W1,
                      const float* __restrict__ b1, const float* __restrict__ W2,
                      const float* __restrict__ b2, float* __restrict__ out,
                      int n_steps)
{
  extern __shared__ SmemLayout smem_raw[];
  SmemLayout& S = smem_raw[0];
  const int tid = threadIdx.x;
  const int b   = blockIdx.x;
  const float* usb = us + (size_t)b * N_K_STEPS * N_INPUT;

  // ---- one-time: W2 -> shared as float2 [k2][o] (conflict-free stage-2 reads)
  for (int idx = tid; idx < 128 * 128; idx += 256) {
    int k2 = idx >> 7, o = idx & 127;
    S.w2[idx] = make_float2(W2[o * 256 + 2 * k2], W2[o * 256 + 2 * k2 + 1]);
  }

  // ---- one-time: this thread's W1 row -> registers (162 regs)
  float2 w1r[81];
  {
    const float* w1row = W1 + tid * FAN_IN;
    #pragma unroll
    for (int p = 0; p < 80; ++p)
      w1r[p] = make_float2(w1row[2 * p], w1row[2 * p + 1]);
    w1r[80] = make_float2(w1row[160], 0.0f);
  }
  const float b1t = b1[tid];
  const float b2t = b2[tid & 127];

  float y_reg = 0.0f;
  if (tid < 128) {
    y_reg = y0[b * N_STATE + tid];
    out[(size_t)b * N_K_STEPS * N_STATE + tid] = y_reg;   // row 0 = y0
  }
  if (tid == 0) {
    float* zf = (float*)S.zs2;
    zf[161] = 0.0f; zf[162] = 0.0f; zf[163] = 0.0f;       // pad for pair 80
  }
  __syncthreads();

  float* zsf = (float*)S.zs2;
  const float2* hs2 = (const float2*)S.hs;

  for (int s = 0; s < n_steps - 1; ++s) {
    const float t0 = ts[s];
    const float t1 = ts[s + 1];
    const float hstep = t1 - t0;

    // ---- step setup: Hermite-interpolated u for stages 1..5
    // (first read of ustg is >=2 barriers later, so no extra sync needed)
    if (tid < 160) {
      int stg = (tid >> 5) + 1;        // 1..5
      int m   = tid & 31;
      float u0v = usb[s * N_INPUT + m];
      float u1v = usb[(s + 1) * N_INPUT + m];
      float hd1 = u1v - u0v;           // h * d[s+1] == u1 - u0 exactly
      float hd0;
      if (s == 0) {
        hd0 = hd1;                     // d[0] == d_orig[0]
      } else {
        float um  = usb[(s - 1) * N_INPUT + m];
        float dtp = t0 - ts[s - 1];
        hd0 = hstep * (u0v - um) / dtp;
      }
      float th = c_C[stg];
      float t2 = th * th, t3 = t2 * th;
      float c00 =  2.f * t3 - 3.f * t2 + 1.f;
      float c01 =        t3 - 2.f * t2 + th;
      float c10 = -2.f * t3 + 3.f * t2;
      float c11 =        t3 -       t2;
      S.ustg[stg][m] = c00 * u0v + c01 * hd0 + c10 * u1v + c11 * hd1;
    }

    for (int st = 0; st < 6; ++st) {
      // ---- (A) assemble z = [t, ytmp, u(theta)] in shared
      if (st == 0) {
        if (tid < 128)       zsf[1 + tid] = y_reg;
        else if (tid < 160)  zsf[129 + (tid - 128)] = usb[s * N_INPUT + (tid - 128)];
        else if (tid == 160) zsf[0] = t0;
      } else {
        if (tid < 128) {
          float kprev = S.partial[tid] + S.partial[tid + 128] + b2t;
          S.ksh[st - 1][tid] = kprev;
          float acc = c_A[st - 1][st - 1] * kprev;
          for (int j = 0; j < st - 1; ++j)
            acc += c_A[st - 1][j] * S.ksh[j][tid];
          zsf[1 + tid] = y_reg + hstep * acc;
        } else if (tid < 160) {
          zsf[129 + (tid - 128)] = S.ustg[st][tid - 128];
        } else if (tid == 160) {
          zsf[0] = t0 + c_C[st] * hstep;
        }
      }
      __syncthreads();

      // ---- (B) hidden layer: h[tid] = tanh(W1[tid,:] . z + b1[tid])
      {
        float2 acc2 = make_float2(0.f, 0.f);
        #pragma unroll
        for (int p = 0; p < 81; ++p)
          acc2 = ffma2f(w1r[p], S.zs2[p], acc2);   // z pair is an LDS.64 broadcast
        S.hs[tid] = tanhf(acc2.x + acc2.y + b1t);
      }
      __syncthreads();

      // ---- (C) output layer partials: 2 threads per output, 128 k each
      {
        const int o    = tid & 127;
        const int base = (tid >> 7) * 64;
        float2 acc2 = make_float2(0.f, 0.f);
        #pragma unroll
        for (int p = 0; p < 64; ++p) {
          float2 wv = S.w2[(base + p) * 128 + o];  // vectorized, conflict-free
          float2 hv = hs2[base + p];               // broadcast
          acc2 = ffma2f(wv, hv, acc2);
        }
        S.partial[tid] = acc2.x + acc2.y;
      }
      __syncthreads();
    }

    // ---- final Runge-Kutta combine + output write
    if (tid < 128) {
      float k5 = S.partial[tid] + S.partial[tid + 128] + b2t;
      float acc = c_B[5] * k5;
      #pragma unroll
      for (int j = 0; j < 5; ++j)
        acc += c_B[j] * S.ksh[j][tid];
      y_reg += hstep * acc;
      out[((size_t)b * N_K_STEPS + (s + 1)) * N_STATE + tid] = y_reg;
    }
    // next iteration's (A)-barrier orders everything; no extra sync required
  }
}

extern "C" void kernel_launch(void* const* d_in, const int* in_sizes, int n_in,
                              void* d_out, int out_size) {
  const float* ts = (const float*)d_in[0];
  const float* y0 = (const float*)d_in[1];
  const float* us = (const float*)d_in[2];
  const float* W1 = (const float*)d_in[3];
  const float* b1 = (const float*)d_in[4];
  const float* W2 = (const float*)d_in[5];
  const float* b2 = (const float*)d_in[6];
  float* out = (float*)d_out;

  const int n_steps = in_sizes[0];             // 512
  const int batch   = in_sizes[1] / N_STATE;   // 64

  const size_t smem_bytes = sizeof(SmemLayout);
  cudaFuncSetAttribute(ode_tsit5_kernel,
                       cudaFuncAttributeMaxDynamicSharedMemorySize, (int)smem_bytes);
  ode_tsit5_kernel<<<batch, 256, smem_bytes>>>(ts, y0, us, W1, b1, W2, b2, out, n_steps);
}